// round 8
// baseline (speedup 1.0000x reference)
#include <cuda_runtime.h>
#include <cstdint>

// Problem constants
#define TT 1024
#define II 64
#define HH 128
#define NTHREADS 512
#define NCTA 128
#define ROWS 4

typedef unsigned long long u64;

// Shared memory layout (bytes), all regions 16B-aligned
#define OFF_WHH 0          // [18][512][16B]  W_hh k=56..127 pair-groups
#define OFF_WIH 147456     // [8][512][16B]   W_ih k=32..63 pair-groups
#define OFF_G   212992     // float [4][512]  raw gate pre-activations
#define OFF_H   221184     // float [4][128]  hidden state
#define OFF_X   223232     // float [2][4][64] x double buffer
#define OFF_WEF 225280     // float [128]     w_eff
#define OFF_BE  225792     // float [1]       b_eff
#define SMEM_BYTES 225824

__device__ __forceinline__ u64 fma2(u64 a, u64 b, u64 c) {
    u64 d;
    asm("fma.rn.f32x2 %0, %1, %2, %3;" : "=l"(d) : "l"(a), "l"(b), "l"(c));
    return d;
}
__device__ __forceinline__ void lds_v2_u64(uint32_t a, u64& v0, u64& v1) {
    asm volatile("ld.shared.v2.u64 {%0,%1}, [%2];" : "=l"(v0), "=l"(v1) : "r"(a));
}
__device__ __forceinline__ float2 unpack2(u64 v) {
    float2 r;
    asm("mov.b64 {%0,%1}, %2;" : "=f"(r.x), "=f"(r.y) : "l"(v));
    return r;
}
__device__ __forceinline__ float sigmoid_f(float x) {
    return __fdividef(1.0f, 1.0f + __expf(-x));
}
__device__ __forceinline__ float tanh_f(float x) {
    return __fdividef(2.0f, 1.0f + __expf(-2.0f * x)) - 1.0f;
}

__global__ void __launch_bounds__(NTHREADS, 1)
lstm_fused_kernel(const float* __restrict__ x,
                  const float* __restrict__ W_ih,
                  const float* __restrict__ W_hh,
                  const float* __restrict__ b_ih,
                  const float* __restrict__ b_hh,
                  const float* __restrict__ W1,
                  const float* __restrict__ b1,
                  const float* __restrict__ W2,
                  const float* __restrict__ b2,
                  float* __restrict__ out)
{
    extern __shared__ char smem[];
    const int t  = threadIdx.x;          // gate column owned by this thread (0..511)
    const int r0 = blockIdx.x * ROWS;    // first batch row of this CTA
    const uint32_t sb = (uint32_t)__cvta_generic_to_shared(smem);

    // ------------- register-resident weights -------------
    // W_hh[t][0..55] as 28 f32x2 pairs; W_ih[t][0..31] as 16 pairs (88 regs)
    u64 wR[28];
    {
        const u64* p = reinterpret_cast<const u64*>(W_hh + t * HH);
        #pragma unroll
        for (int q = 0; q < 28; ++q) wR[q] = p[q];
    }
    u64 wI[16];
    {
        const u64* p = reinterpret_cast<const u64*>(W_ih + t * II);
        #pragma unroll
        for (int q = 0; q < 16; ++q) wI[q] = p[q];
    }
    const float biasv = b_ih[t] + b_hh[t];

    // ------------- smem-resident weight tails -------------
    // layout [pair-group p][thread t] of 16B: group p holds k = base+4p .. base+4p+3
    {
        const float4* ph = reinterpret_cast<const float4*>(W_hh + t * HH + 56);
        #pragma unroll
        for (int p = 0; p < 18; ++p)
            *reinterpret_cast<float4*>(smem + OFF_WHH + p * 8192 + t * 16) = ph[p];
        const float4* pi = reinterpret_cast<const float4*>(W_ih + t * II + 32);
        #pragma unroll
        for (int p = 0; p < 8; ++p)
            *reinterpret_cast<float4*>(smem + OFF_WIH + p * 8192 + t * 16) = pi[p];
    }

    float* gs = reinterpret_cast<float*>(smem + OFF_G);
    float* hs = reinterpret_cast<float*>(smem + OFF_H);
    float* xs = reinterpret_cast<float*>(smem + OFF_X);
    float* weff = reinterpret_cast<float*>(smem + OFF_WEF);
    float* beff = reinterpret_cast<float*>(smem + OFF_BE);

    // h0 = 0 (4*128 = 512 floats, one per thread)
    hs[t] = 0.0f;

    // w_eff = W2 @ W1 (1x128), b_eff = W2@b1 + b2   (once, cheap)
    if (t < 128) {
        float s = 0.0f;
        #pragma unroll 4
        for (int m = 0; m < 256; ++m) s += W2[m] * W1[m * HH + t];
        weff[t] = s;
    }
    if (t == 0) {
        float s = b2[0];
        for (int m = 0; m < 256; ++m) s += W2[m] * b1[m];
        beff[0] = s;
    }

    // preload x for step 0 into buffer 0 (threads 0..255: row = t>>6, k = t&63)
    const float* xptr = x + (size_t)(r0 + (t >> 6)) * (TT * II) + (t & 63);
    if (t < 256) xs[t] = xptr[0];

    float cval = 0.0f;            // c state for (row = t>>7, col = t&127)
    const int br = t >> 7;
    const int bj = t & 127;

    const uint32_t aWH = sb + OFF_WHH + t * 16;
    const uint32_t aWI = sb + OFF_WIH + t * 16;
    const uint32_t aH  = sb + OFF_H;
    const uint32_t aX  = sb + OFF_X;

    __syncthreads();

    #pragma unroll 1
    for (int s = 0; s < TT; ++s) {
        const uint32_t aXb = aX + (s & 1) * 1024;

        // prefetch x for step s+1 into the other buffer (consumed after end-of-step sync)
        float xpre = 0.0f;
        {
            int sn = (s + 1 < TT) ? (s + 1) : s;
            if (t < 256) xpre = __ldg(xptr + sn * II);
        }

        // ---------------- phase A: gate pre-activations ----------------
        u64 acc[ROWS];
        #pragma unroll
        for (int r = 0; r < ROWS; ++r) acc[r] = 0ull;

        // x-part, register weights (k = 0..31)
        #pragma unroll
        for (int p = 0; p < 8; ++p) {
            #pragma unroll
            for (int r = 0; r < ROWS; ++r) {
                u64 a, b;
                lds_v2_u64(aXb + r * 256 + p * 16, a, b);
                acc[r] = fma2(wI[2 * p], a, acc[r]);
                acc[r] = fma2(wI[2 * p + 1], b, acc[r]);
            }
        }
        // x-part, smem weights (k = 32..63)
        #pragma unroll
        for (int p = 0; p < 8; ++p) {
            u64 w0, w1;
            lds_v2_u64(aWI + p * 8192, w0, w1);
            #pragma unroll
            for (int r = 0; r < ROWS; ++r) {
                u64 a, b;
                lds_v2_u64(aXb + r * 256 + 128 + p * 16, a, b);
                acc[r] = fma2(w0, a, acc[r]);
                acc[r] = fma2(w1, b, acc[r]);
            }
        }
        // h-part, register weights (k = 0..55)
        #pragma unroll
        for (int p = 0; p < 14; ++p) {
            #pragma unroll
            for (int r = 0; r < ROWS; ++r) {
                u64 a, b;
                lds_v2_u64(aH + r * 512 + p * 16, a, b);
                acc[r] = fma2(wR[2 * p], a, acc[r]);
                acc[r] = fma2(wR[2 * p + 1], b, acc[r]);
            }
        }
        // h-part, smem weights (k = 56..127)
        #pragma unroll
        for (int p = 0; p < 18; ++p) {
            u64 w0, w1;
            lds_v2_u64(aWH + p * 8192, w0, w1);
            #pragma unroll
            for (int r = 0; r < ROWS; ++r) {
                u64 a, b;
                lds_v2_u64(aH + r * 512 + 224 + p * 16, a, b);
                acc[r] = fma2(w0, a, acc[r]);
                acc[r] = fma2(w1, b, acc[r]);
            }
        }

        #pragma unroll
        for (int r = 0; r < ROWS; ++r) {
            float2 f = unpack2(acc[r]);
            gs[r * 512 + t] = (f.x + f.y) + biasv;
        }

        // stash prefetched x (write to the (s+1)&1 buffer; safe: last read of that
        // buffer was phase A of step s-1, separated by the end-of-(s-1) sync)
        if (t < 256) xs[((s + 1) & 1) * 256 + t] = xpre;

        __syncthreads();

        // ---------------- phase B: activations + state update ----------------
        {
            float gi = gs[br * 512 + bj];
            float gf = gs[br * 512 + 128 + bj];
            float gg = gs[br * 512 + 256 + bj];
            float go = gs[br * 512 + 384 + bj];
            float ig = sigmoid_f(gi);
            float fg = sigmoid_f(gf);
            float gv = tanh_f(gg);
            float og = sigmoid_f(go);
            cval = fg * cval + ig * gv;
            hs[br * HH + bj] = og * tanh_f(cval);
        }
        __syncthreads();
    }

    // ---------------- fused fc1+fc2 epilogue ----------------
    if (t < ROWS) {
        float s = beff[0];
        #pragma unroll 8
        for (int j = 0; j < HH; ++j) s += hs[t * HH + j] * weff[j];
        out[r0 + t] = s;
    }
}

extern "C" void kernel_launch(void* const* d_in, const int* in_sizes, int n_in,
                              void* d_out, int out_size) {
    const float* x    = (const float*)d_in[0];
    const float* W_ih = (const float*)d_in[1];
    const float* W_hh = (const float*)d_in[2];
    const float* b_ih = (const float*)d_in[3];
    const float* b_hh = (const float*)d_in[4];
    const float* W1   = (const float*)d_in[5];
    const float* b1   = (const float*)d_in[6];
    const float* W2   = (const float*)d_in[7];
    const float* b2   = (const float*)d_in[8];
    float* out = (float*)d_out;

    cudaFuncSetAttribute(lstm_fused_kernel,
                         cudaFuncAttributeMaxDynamicSharedMemorySize, SMEM_BYTES);

    lstm_fused_kernel<<<NCTA, NTHREADS, SMEM_BYTES>>>(
        x, W_ih, W_hh, b_ih, b_hh, W1, b1, W2, b2, out);
}